// round 15
// baseline (speedup 1.0000x reference)
#include <cuda_runtime.h>
#include <cuda_bf16.h>
#include <cuda_fp16.h>
#include <cstdint>

// Problem constants
#define B_   32
#define S_   512
#define D_   768
#define H_   12
#define HD_  64
#define M_   (B_ * S_)       // 16384 rows
#define NQKV (3 * D_)        // 2304

#define LO_SCALE   4096.0f
#define LO_INV     2.44140625e-4f   // 1/4096

// ---------------------------------------------------------------------------
// Scratch (device globals per allocation rules)
// ---------------------------------------------------------------------------
__device__ __half g_xh[(size_t)M_ * D_];     // x split hi (fp16)
__device__ __half g_xl[(size_t)M_ * D_];     // x split lo (fp16, x4096)
__device__ __half g_ah[(size_t)M_ * D_];     // attn out hi [M,D] (fp16)
__device__ __half g_al[(size_t)M_ * D_];     // attn out lo (fp16, x4096)
__device__ __half g_qwh[(size_t)NQKV * D_];
__device__ __half g_qwl[(size_t)NQKV * D_];
__device__ __half g_pwh[(size_t)D_ * D_];
__device__ __half g_pwl[(size_t)D_ * D_];
// head-separated QKV [B,H,S,64], hi/lo BF16 (attention unchanged; Q pre-scaled)
#define QKVE ((size_t)B_ * H_ * S_ * HD_)
__device__ __nv_bfloat16 g_qh[QKVE];
__device__ __nv_bfloat16 g_ql[QKVE];
__device__ __nv_bfloat16 g_kh[QKVE];
__device__ __nv_bfloat16 g_kl[QKVE];
__device__ __nv_bfloat16 g_vh[QKVE];
__device__ __nv_bfloat16 g_vl[QKVE];

// ---------------------------------------------------------------------------
// Helpers
// ---------------------------------------------------------------------------
__device__ __forceinline__ uint32_t smem_u32(const void* p) {
    uint32_t a;
    asm("{ .reg .u64 t; cvta.to.shared.u64 t, %1; cvt.u32.u64 %0, t; }" : "=r"(a) : "l"(p));
    return a;
}
#define CP16(dst, src) \
    asm volatile("cp.async.cg.shared.global [%0], [%1], 16;\n" :: "r"(dst), "l"(src))
#define CP_COMMIT()  asm volatile("cp.async.commit_group;\n" ::: "memory")
#define CP_WAIT1()   asm volatile("cp.async.wait_group 1;\n" ::: "memory")

#define LDSM4(R, addr) \
    asm volatile("ldmatrix.sync.aligned.m8n8.x4.shared.b16 {%0,%1,%2,%3}, [%4];" \
                 : "=r"((R)[0]), "=r"((R)[1]), "=r"((R)[2]), "=r"((R)[3]) : "r"(addr))
#define LDSM4T(R, addr) \
    asm volatile("ldmatrix.sync.aligned.m8n8.x4.trans.shared.b16 {%0,%1,%2,%3}, [%4];" \
                 : "=r"((R)[0]), "=r"((R)[1]), "=r"((R)[2]), "=r"((R)[3]) : "r"(addr))

// bf16 MMA, f32 accumulate (attention)
#define MMA16816(D, A, b0v, b1v) \
    asm volatile("mma.sync.aligned.m16n8k16.row.col.f32.bf16.bf16.f32 " \
                 "{%0,%1,%2,%3},{%4,%5,%6,%7},{%8,%9},{%0,%1,%2,%3};" \
                 : "+f"((D)[0]), "+f"((D)[1]), "+f"((D)[2]), "+f"((D)[3]) \
                 : "r"((A)[0]), "r"((A)[1]), "r"((A)[2]), "r"((A)[3]), \
                   "r"(b0v), "r"(b1v))

// fp16 MMA, f32 accumulate (GEMM main term)
#define MMA16816_HF32(D, A, b0v, b1v) \
    asm volatile("mma.sync.aligned.m16n8k16.row.col.f32.f16.f16.f32 " \
                 "{%0,%1,%2,%3},{%4,%5,%6,%7},{%8,%9},{%0,%1,%2,%3};" \
                 : "+f"((D)[0]), "+f"((D)[1]), "+f"((D)[2]), "+f"((D)[3]) \
                 : "r"((A)[0]), "r"((A)[1]), "r"((A)[2]), "r"((A)[3]), \
                   "r"(b0v), "r"(b1v))

// fp16 MMA, f16 accumulate (GEMM correction terms)
#define MMA16816_HF16(D, A, b0v, b1v) \
    asm volatile("mma.sync.aligned.m16n8k16.row.col.f16.f16.f16.f16 " \
                 "{%0,%1},{%2,%3,%4,%5},{%6,%7},{%0,%1};" \
                 : "+r"((D)[0]), "+r"((D)[1]) \
                 : "r"((A)[0]), "r"((A)[1]), "r"((A)[2]), "r"((A)[3]), \
                   "r"(b0v), "r"(b1v))

__device__ __forceinline__ uint32_t pack_bf16x2(float a, float b) {
    __nv_bfloat162 v = __floats2bfloat162_rn(a, b);
    return *(uint32_t*)&v;
}
__device__ __forceinline__ uint32_t pack_h2(float a, float b) {
    __half2 v = __floats2half2_rn(a, b);
    return *(uint32_t*)&v;
}

// ---------------------------------------------------------------------------
// Split fp32 -> fp16 hi/lo (lo scaled by 4096 to stay in normal range)
// ---------------------------------------------------------------------------
__global__ __launch_bounds__(256) void split_kernel(
    const float* __restrict__ src, __half* __restrict__ hi,
    __half* __restrict__ lo, int n4)
{
    int i = blockIdx.x * blockDim.x + threadIdx.x;
    if (i >= n4) return;
    float4 v = ((const float4*)src)[i];
    union { __half b[4]; uint2 u; } uh, ul;
    float f[4] = {v.x, v.y, v.z, v.w};
#pragma unroll
    for (int j = 0; j < 4; j++) {
        __half h = __float2half_rn(f[j]);
        uh.b[j] = h;
        ul.b[j] = __float2half_rn((f[j] - __half2float(h)) * LO_SCALE);
    }
    ((uint2*)hi)[i] = uh.u;
    ((uint2*)lo)[i] = ul.u;
}

// ---------------------------------------------------------------------------
// fp16x2 mixed-accumulate GEMM: C = A@W^T + bias
// 512 threads, 16 warps as 4(M) x 4(N), warp tile 32x32 (acc 48 regs ->
// spill-free at the 128-reg/thread RF limit, 4 warps/SMSP).
// CTA tile 128x128, KT=64, NSTAGE=3 (216KB smem, 1 CTA/SM), single barrier.
// MODE 0: fp32 C store.  MODE 1: QKV split-store to bf16 head-sep arrays.
// ---------------------------------------------------------------------------
#define KT        64
#define RSTRIDE   144
#define TILE_B    (128 * RSTRIDE)     // 18432
#define STAGE_B   (4 * TILE_B)        // 73728
#define NSTAGE    3
#define GEMM_SMEM (NSTAGE * STAGE_B)  // 221184
#define GTHREADS  512

template<int MODE>
__global__ __launch_bounds__(GTHREADS, 1) void gemm_mma_kernel(
    const __half* __restrict__ Ah, const __half* __restrict__ Al,
    const __half* __restrict__ Wh, const __half* __restrict__ Wl,
    const float* __restrict__ bias, float* __restrict__ C, int N, int K,
    __nv_bfloat16* __restrict__ oqh, __nv_bfloat16* __restrict__ oql,
    __nv_bfloat16* __restrict__ okh, __nv_bfloat16* __restrict__ okl,
    __nv_bfloat16* __restrict__ ovh, __nv_bfloat16* __restrict__ ovl)
{
    extern __shared__ char smem[];
    const uint32_t sb = smem_u32(smem);
    const int tid  = threadIdx.x;
    const int wid  = tid >> 5;
    const int lane = tid & 31;
    const int wm   = wid & 3;        // 0..3 -> 32-row slice
    const int wn   = wid >> 2;       // 0..3 -> 32-col slice
    const int m0   = blockIdx.y * 128;
    const int n0   = blockIdx.x * 128;

    float    accm[2][4][4];          // main term, f32
    uint32_t accc[2][4][2];          // correction, f16x2 pairs
#pragma unroll
    for (int a = 0; a < 2; a++)
#pragma unroll
        for (int b = 0; b < 4; b++) {
#pragma unroll
            for (int c = 0; c < 4; c++) accm[a][b][c] = 0.f;
            accc[a][b][0] = 0u; accc[a][b][1] = 0u;
        }

    const int nkc = K / KT;   // 12

    // ---- stage loader: 4096 16B-chunks, 8 per thread ----
    auto issue_stage = [&](int kc, int s) {
        const int k0 = kc * KT;
        const uint32_t sbase = sb + s * STAGE_B;
#pragma unroll
        for (int it = 0; it < 8; it++) {
            const int lin  = it * GTHREADS + tid;  // 0..4095
            const int tile = lin >> 10;
            const int idx  = lin & 1023;
            const int r    = idx >> 3;
            const int c    = idx & 7;
            const uint32_t dst = sbase + tile * TILE_B + r * RSTRIDE + c * 16;
            const __half* src;
            if (tile == 0)      src = Ah + (size_t)(m0 + r) * K + k0 + c * 8;
            else if (tile == 1) src = Al + (size_t)(m0 + r) * K + k0 + c * 8;
            else if (tile == 2) src = Wh + (size_t)(n0 + r) * K + k0 + c * 8;
            else                src = Wl + (size_t)(n0 + r) * K + k0 + c * 8;
            CP16(dst, src);
        }
        CP_COMMIT();
    };

    issue_stage(0, 0);
    issue_stage(1, 1);

    const int arow_base = wm * 32 + (lane & 15);
    const int aco       = (lane >> 4);
    const int brow_base = wn * 32 + (((lane >> 4) << 3) | (lane & 7));
    const int bco       = ((lane >> 3) & 1);

    for (int kc = 0; kc < nkc; kc++) {
        CP_WAIT1();
        __syncthreads();
        if (kc + 2 < nkc) issue_stage(kc + 2, (kc + 2) % NSTAGE);
        else CP_COMMIT();

        const uint32_t sbase = sb + (kc % NSTAGE) * STAGE_B;
#pragma unroll
        for (int j = 0; j < 4; j++) {          // four k16 steps per stage
            uint32_t ah[2][4], al[2][4];
#pragma unroll
            for (int mt = 0; mt < 2; mt++) {
                const uint32_t ad = sbase + (arow_base + mt * 16) * RSTRIDE
                                  + j * 32 + aco * 16;
                LDSM4(ah[mt], ad);
                LDSM4(al[mt], ad + TILE_B);
            }
#pragma unroll
            for (int ng = 0; ng < 2; ng++) {   // two 16-col groups per warp
                uint32_t bh[4], bl[4];
                const uint32_t bd = sbase + 2 * TILE_B
                                  + (brow_base + ng * 16) * RSTRIDE
                                  + j * 32 + bco * 16;
                LDSM4(bh, bd);
                LDSM4(bl, bd + TILE_B);
#pragma unroll
                for (int mt = 0; mt < 2; mt++)
#pragma unroll
                    for (int p = 0; p < 2; p++) {
                        MMA16816_HF32(accm[mt][ng * 2 + p], ah[mt],
                                      bh[2 * p], bh[2 * p + 1]);
                        MMA16816_HF16(accc[mt][ng * 2 + p], ah[mt],
                                      bl[2 * p], bl[2 * p + 1]);
                        MMA16816_HF16(accc[mt][ng * 2 + p], al[mt],
                                      bh[2 * p], bh[2 * p + 1]);
                    }
            }
        }
        // no trailing barrier: next iteration's top barrier protects slot reuse
    }

    const int g = lane >> 2;
    const int t = lane & 3;
#pragma unroll
    for (int mt = 0; mt < 2; mt++) {
        const int row0 = m0 + wm * 32 + mt * 16 + g;
#pragma unroll
        for (int nt = 0; nt < 4; nt++) {
            const int col = n0 + wn * 32 + nt * 8 + t * 2;
            const float2 bv = *(const float2*)&bias[col];
            const float2 c0 = __half22float2(*(__half2*)&accc[mt][nt][0]);
            const float2 c1 = __half22float2(*(__half2*)&accc[mt][nt][1]);
            float v00 = accm[mt][nt][0] + c0.x * LO_INV + bv.x;
            float v01 = accm[mt][nt][1] + c0.y * LO_INV + bv.y;
            float v10 = accm[mt][nt][2] + c1.x * LO_INV + bv.x;
            float v11 = accm[mt][nt][3] + c1.y * LO_INV + bv.y;
            if (MODE == 0) {
                *(float2*)&C[(size_t)row0 * N + col]       = make_float2(v00, v01);
                *(float2*)&C[(size_t)(row0 + 8) * N + col] = make_float2(v10, v11);
            } else {
                const int sec = col / 768;
                const int rem = col - sec * 768;
                const int h   = rem >> 6;
                const int d   = rem & 63;
                if (sec == 0) { v00 *= 0.125f; v01 *= 0.125f; v10 *= 0.125f; v11 *= 0.125f; }
                __nv_bfloat16* dh = (sec == 0) ? oqh : (sec == 1) ? okh : ovh;
                __nv_bfloat16* dl = (sec == 0) ? oql : (sec == 1) ? okl : ovl;
#pragma unroll
                for (int rr = 0; rr < 2; rr++) {
                    const int row = row0 + rr * 8;
                    const float a0 = rr ? v10 : v00, a1 = rr ? v11 : v01;
                    const int bb = row >> 9, ss = row & 511;
                    const size_t idx = (((size_t)bb * H_ + h) * S_ + ss) * HD_ + d;
                    const float h0 = __bfloat162float(__float2bfloat16_rn(a0));
                    const float h1 = __bfloat162float(__float2bfloat16_rn(a1));
                    *(uint32_t*)&dh[idx] = pack_bf16x2(a0, a1);
                    *(uint32_t*)&dl[idx] = pack_bf16x2(a0 - h0, a1 - h1);
                }
            }
        }
    }
}

// ---------------------------------------------------------------------------
// Tensor-core flash attention (bf16 core unchanged; epilogue emits fp16
// hi + 4096-scaled lo for the fp16 proj GEMM). Measured-good since R6.
// Grid (S/128, H, B), 256 threads (8 warps x 16 q-rows). kv tiles of 64.
// ---------------------------------------------------------------------------
#define ARS      144
#define QT_B     (128 * ARS)
#define AT_B     (64 * ARS)
#define ASTAGE_B (4 * AT_B)
#define ATT_SMEM (2 * QT_B + 2 * ASTAGE_B)

__global__ __launch_bounds__(256, 2) void attn_tc_kernel()
{
    extern __shared__ char smem[];
    const uint32_t sb = smem_u32(smem);
    const uint32_t QH = sb, QL = sb + QT_B;
    const int tid  = threadIdx.x;
    const int wid  = tid >> 5;
    const int lane = tid & 31;
    const int g    = lane >> 2;
    const int t    = lane & 3;

    const int qt = blockIdx.x;
    const int h  = blockIdx.y;
    const int b  = blockIdx.z;

    const size_t headbase = ((size_t)b * H_ + h) * S_ * HD_;
    const size_t qbase    = headbase + (size_t)qt * 128 * HD_;

#pragma unroll
    for (int it = 0; it < 8; it++) {
        const int lin  = it * 256 + tid;
        const int half = lin >> 10;
        const int idx  = lin & 1023;
        const int r    = idx >> 3;
        const int c    = idx & 7;
        const uint32_t dst = (half ? QL : QH) + r * ARS + c * 16;
        const __nv_bfloat16* src = (half ? g_ql : g_qh) + qbase + (size_t)r * HD_ + c * 8;
        CP16(dst, src);
    }
    CP_COMMIT();

    auto issue_kv = [&](int kt, int s) {
        const uint32_t sbase = sb + 2 * QT_B + s * ASTAGE_B;
        const size_t kvb = headbase + (size_t)kt * 64 * HD_;
#pragma unroll
        for (int it = 0; it < 8; it++) {
            const int lin  = it * 256 + tid;
            const int tile = lin >> 9;
            const int idx  = lin & 511;
            const int r    = idx >> 3;
            const int c    = idx & 7;
            const uint32_t dst = sbase + tile * AT_B + r * ARS + c * 16;
            const __nv_bfloat16* base =
                (tile == 0) ? g_kh : (tile == 1) ? g_kl : (tile == 2) ? g_vh : g_vl;
            CP16(dst, base + kvb + (size_t)r * HD_ + c * 8);
        }
        CP_COMMIT();
    };

    issue_kv(0, 0);
    issue_kv(1, 1);

    float oacc[8][4];
#pragma unroll
    for (int j = 0; j < 8; j++)
#pragma unroll
        for (int c = 0; c < 4; c++) oacc[j][c] = 0.f;
    float mrow[2] = {-1e30f, -1e30f};
    float lrow[2] = {0.f, 0.f};

    const int qa_row = wid * 16 + (lane & 15);
    const int qa_k   = (lane >> 4) * 8;
    const int kb_row = (lane & 7) + 8 * (lane >> 4);
    const int kb_k   = ((lane >> 3) & 1) * 8;
    const int vb_row = (lane & 15);
    const int vb_d   = (lane >> 4) * 8;

    for (int kt = 0; kt < 8; kt++) {
        CP_WAIT1();
        __syncthreads();
        const uint32_t st  = sb + 2 * QT_B + (kt & 1) * ASTAGE_B;
        const uint32_t KHs = st, VHs = st + 2 * AT_B;

        float sacc[8][4];
#pragma unroll
        for (int j = 0; j < 8; j++)
#pragma unroll
            for (int c = 0; c < 4; c++) sacc[j][c] = 0.f;

#pragma unroll
        for (int ks = 0; ks < 4; ks++) {
            uint32_t qh[4], ql[4];
            const uint32_t qa = QH + qa_row * ARS + (ks * 16 + qa_k) * 2;
            LDSM4(qh, qa);
            LDSM4(ql, qa + QT_B);
#pragma unroll
            for (int jp = 0; jp < 4; jp++) {
                uint32_t kh[4], kl[4];
                const uint32_t ka = KHs + (jp * 16 + kb_row) * ARS + (ks * 16 + kb_k) * 2;
                LDSM4(kh, ka);
                LDSM4(kl, ka + AT_B);
                MMA16816(sacc[2 * jp],     qh, kh[0], kh[1]);
                MMA16816(sacc[2 * jp + 1], qh, kh[2], kh[3]);
                MMA16816(sacc[2 * jp],     qh, kl[0], kl[1]);
                MMA16816(sacc[2 * jp + 1], qh, kl[2], kl[3]);
                MMA16816(sacc[2 * jp],     ql, kh[0], kh[1]);
                MMA16816(sacc[2 * jp + 1], ql, kh[2], kh[3]);
            }
        }

        float mloc0 = -1e30f, mloc1 = -1e30f;
#pragma unroll
        for (int j = 0; j < 8; j++) {
            mloc0 = fmaxf(mloc0, fmaxf(sacc[j][0], sacc[j][1]));
            mloc1 = fmaxf(mloc1, fmaxf(sacc[j][2], sacc[j][3]));
        }
        mloc0 = fmaxf(mloc0, __shfl_xor_sync(0xffffffffu, mloc0, 1));
        mloc0 = fmaxf(mloc0, __shfl_xor_sync(0xffffffffu, mloc0, 2));
        mloc1 = fmaxf(mloc1, __shfl_xor_sync(0xffffffffu, mloc1, 1));
        mloc1 = fmaxf(mloc1, __shfl_xor_sync(0xffffffffu, mloc1, 2));

        const float nm0 = fmaxf(mrow[0], mloc0);
        const float nm1 = fmaxf(mrow[1], mloc1);
        const float cr0 = __expf(mrow[0] - nm0);
        const float cr1 = __expf(mrow[1] - nm1);
        mrow[0] = nm0; mrow[1] = nm1;
        lrow[0] *= cr0; lrow[1] *= cr1;
#pragma unroll
        for (int j = 0; j < 8; j++) {
            oacc[j][0] *= cr0; oacc[j][1] *= cr0;
            oacc[j][2] *= cr1; oacc[j][3] *= cr1;
        }
        float ll0 = 0.f, ll1 = 0.f;
#pragma unroll
        for (int j = 0; j < 8; j++) {
            sacc[j][0] = __expf(sacc[j][0] - nm0);
            sacc[j][1] = __expf(sacc[j][1] - nm0);
            sacc[j][2] = __expf(sacc[j][2] - nm1);
            sacc[j][3] = __expf(sacc[j][3] - nm1);
            ll0 += sacc[j][0] + sacc[j][1];
            ll1 += sacc[j][2] + sacc[j][3];
        }
        ll0 += __shfl_xor_sync(0xffffffffu, ll0, 1);
        ll0 += __shfl_xor_sync(0xffffffffu, ll0, 2);
        ll1 += __shfl_xor_sync(0xffffffffu, ll1, 1);
        ll1 += __shfl_xor_sync(0xffffffffu, ll1, 2);
        lrow[0] += ll0; lrow[1] += ll1;

#pragma unroll
        for (int i = 0; i < 4; i++) {
            uint32_t pah[4], pal[4];
#pragma unroll
            for (int hf = 0; hf < 2; hf++) {
                const float* sp = sacc[2 * i + hf];
                float h0 = __bfloat162float(__float2bfloat16_rn(sp[0]));
                float h1 = __bfloat162float(__float2bfloat16_rn(sp[1]));
                float h2 = __bfloat162float(__float2bfloat16_rn(sp[2]));
                float h3 = __bfloat162float(__float2bfloat16_rn(sp[3]));
                pah[2 * hf]     = pack_bf16x2(sp[0], sp[1]);
                pah[2 * hf + 1] = pack_bf16x2(sp[2], sp[3]);
                pal[2 * hf]     = pack_bf16x2(sp[0] - h0, sp[1] - h1);
                pal[2 * hf + 1] = pack_bf16x2(sp[2] - h2, sp[3] - h3);
            }
            uint32_t Ah4[4] = {pah[0], pah[1], pah[2], pah[3]};
            uint32_t Al4[4] = {pal[0], pal[1], pal[2], pal[3]};
#pragma unroll
            for (int dv = 0; dv < 4; dv++) {
                uint32_t vh[4], vl[4];
                const uint32_t va = VHs + (i * 16 + vb_row) * ARS + (dv * 16 + vb_d) * 2;
                LDSM4T(vh, va);
                LDSM4T(vl, va + AT_B);
                MMA16816(oacc[2 * dv],     Ah4, vh[0], vh[1]);
                MMA16816(oacc[2 * dv + 1], Ah4, vh[2], vh[3]);
                MMA16816(oacc[2 * dv],     Ah4, vl[0], vl[1]);
                MMA16816(oacc[2 * dv + 1], Ah4, vl[2], vl[3]);
                MMA16816(oacc[2 * dv],     Al4, vh[0], vh[1]);
                MMA16816(oacc[2 * dv + 1], Al4, vh[2], vh[3]);
            }
        }

        __syncthreads();
        if (kt + 2 < 8) issue_kv(kt + 2, kt & 1);
    }

    // epilogue: normalize, split to fp16 hi + scaled lo for proj GEMM
    const float inv0 = 1.f / lrow[0];
    const float inv1 = 1.f / lrow[1];
    const int s0 = qt * 128 + wid * 16 + g;
#pragma unroll
    for (int rr = 0; rr < 2; rr++) {
        const int srow = s0 + rr * 8;
        const float inv = rr ? inv1 : inv0;
        const size_t obase = ((size_t)b * S_ + srow) * D_ + h * HD_;
#pragma unroll
        for (int j = 0; j < 8; j++) {
            const int d = j * 8 + t * 2;
            const float a0 = oacc[j][2 * rr]     * inv;
            const float a1 = oacc[j][2 * rr + 1] * inv;
            const float h0 = __half2float(__float2half_rn(a0));
            const float h1 = __half2float(__float2half_rn(a1));
            *(uint32_t*)&g_ah[obase + d] = pack_h2(a0, a1);
            *(uint32_t*)&g_al[obase + d] = pack_h2((a0 - h0) * LO_SCALE,
                                                   (a1 - h1) * LO_SCALE);
        }
    }
}

// ---------------------------------------------------------------------------
extern "C" void kernel_launch(void* const* d_in, const int* in_sizes, int n_in,
                              void* d_out, int out_size)
{
    const float* x      = (const float*)d_in[0];
    const float* qkv_w  = (const float*)d_in[1];
    const float* qkv_b  = (const float*)d_in[2];
    const float* proj_w = (const float*)d_in[3];
    const float* proj_b = (const float*)d_in[4];
    float* out = (float*)d_out;

    __half *xh, *xl, *ah, *al, *qwh, *qwl, *pwh, *pwl;
    __nv_bfloat16 *qh, *ql, *kh, *kl, *vh, *vl;
    cudaGetSymbolAddress((void**)&xh, g_xh);
    cudaGetSymbolAddress((void**)&xl, g_xl);
    cudaGetSymbolAddress((void**)&ah, g_ah);
    cudaGetSymbolAddress((void**)&al, g_al);
    cudaGetSymbolAddress((void**)&qwh, g_qwh);
    cudaGetSymbolAddress((void**)&qwl, g_qwl);
    cudaGetSymbolAddress((void**)&pwh, g_pwh);
    cudaGetSymbolAddress((void**)&pwl, g_pwl);
    cudaGetSymbolAddress((void**)&qh, g_qh);
    cudaGetSymbolAddress((void**)&ql, g_ql);
    cudaGetSymbolAddress((void**)&kh, g_kh);
    cudaGetSymbolAddress((void**)&kl, g_kl);
    cudaGetSymbolAddress((void**)&vh, g_vh);
    cudaGetSymbolAddress((void**)&vl, g_vl);

    cudaFuncSetAttribute(gemm_mma_kernel<0>,
                         cudaFuncAttributeMaxDynamicSharedMemorySize, GEMM_SMEM);
    cudaFuncSetAttribute(gemm_mma_kernel<1>,
                         cudaFuncAttributeMaxDynamicSharedMemorySize, GEMM_SMEM);
    cudaFuncSetAttribute(attn_tc_kernel,
                         cudaFuncAttributeMaxDynamicSharedMemorySize, ATT_SMEM);

    // 1) splits (fp16 hi + 4096-scaled lo)
    {
        int n4 = (M_ * D_) / 4;
        split_kernel<<<(n4 + 255) / 256, 256>>>(x, xh, xl, n4);
        n4 = (NQKV * D_) / 4;
        split_kernel<<<(n4 + 255) / 256, 256>>>(qkv_w, qwh, qwl, n4);
        n4 = (D_ * D_) / 4;
        split_kernel<<<(n4 + 255) / 256, 256>>>(proj_w, pwh, pwl, n4);
    }

    // 2) QKV projection -> bf16 head-separated (Q pre-scaled)
    {
        dim3 g(NQKV / 128, M_ / 128);
        gemm_mma_kernel<1><<<g, GTHREADS, GEMM_SMEM>>>(xh, xl, qwh, qwl, qkv_b,
                                                       nullptr, NQKV, D_,
                                                       qh, ql, kh, kl, vh, vl);
    }

    // 3) tensor-core flash attention -> g_ah/g_al (fp16)
    {
        dim3 g(S_ / 128, H_, B_);
        attn_tc_kernel<<<g, 256, ATT_SMEM>>>();
    }

    // 4) output projection
    {
        dim3 g(D_ / 128, M_ / 128);
        gemm_mma_kernel<0><<<g, GTHREADS, GEMM_SMEM>>>(ah, al, pwh, pwl, proj_b, out,
                                                       D_, D_,
                                                       nullptr, nullptr, nullptr,
                                                       nullptr, nullptr, nullptr);
    }
}

// round 16
// speedup vs baseline: 1.1950x; 1.1950x over previous
#include <cuda_runtime.h>
#include <cuda_bf16.h>
#include <cuda_fp16.h>
#include <cstdint>

// Problem constants
#define B_   32
#define S_   512
#define D_   768
#define H_   12
#define HD_  64
#define M_   (B_ * S_)       // 16384 rows
#define NQKV (3 * D_)        // 2304

#define LO_SCALE   4096.0f
#define LO_INV     2.44140625e-4f   // 1/4096

// ---------------------------------------------------------------------------
// Scratch (device globals per allocation rules)
// ---------------------------------------------------------------------------
__device__ __half g_xh[(size_t)M_ * D_];     // x -> fp16 (A side, no lo)
__device__ __half g_ah[(size_t)M_ * D_];     // attn out [M,D] fp16 (A side)
__device__ __half g_qwh[(size_t)NQKV * D_];
__device__ __half g_qwl[(size_t)NQKV * D_];  // x4096
__device__ __half g_pwh[(size_t)D_ * D_];
__device__ __half g_pwl[(size_t)D_ * D_];    // x4096
// head-separated QKV [B,H,S,64], hi/lo BF16 (attention 3-term; Q pre-scaled)
#define QKVE ((size_t)B_ * H_ * S_ * HD_)
__device__ __nv_bfloat16 g_qh[QKVE];
__device__ __nv_bfloat16 g_ql[QKVE];
__device__ __nv_bfloat16 g_kh[QKVE];
__device__ __nv_bfloat16 g_kl[QKVE];
__device__ __nv_bfloat16 g_vh[QKVE];
__device__ __nv_bfloat16 g_vl[QKVE];

// ---------------------------------------------------------------------------
// Helpers
// ---------------------------------------------------------------------------
__device__ __forceinline__ uint32_t smem_u32(const void* p) {
    uint32_t a;
    asm("{ .reg .u64 t; cvta.to.shared.u64 t, %1; cvt.u32.u64 %0, t; }" : "=r"(a) : "l"(p));
    return a;
}
#define CP16(dst, src) \
    asm volatile("cp.async.cg.shared.global [%0], [%1], 16;\n" :: "r"(dst), "l"(src))
#define CP_COMMIT()  asm volatile("cp.async.commit_group;\n" ::: "memory")
#define CP_WAIT1()   asm volatile("cp.async.wait_group 1;\n" ::: "memory")

#define LDSM4(R, addr) \
    asm volatile("ldmatrix.sync.aligned.m8n8.x4.shared.b16 {%0,%1,%2,%3}, [%4];" \
                 : "=r"((R)[0]), "=r"((R)[1]), "=r"((R)[2]), "=r"((R)[3]) : "r"(addr))
#define LDSM4T(R, addr) \
    asm volatile("ldmatrix.sync.aligned.m8n8.x4.trans.shared.b16 {%0,%1,%2,%3}, [%4];" \
                 : "=r"((R)[0]), "=r"((R)[1]), "=r"((R)[2]), "=r"((R)[3]) : "r"(addr))

// bf16 MMA, f32 accumulate (attention)
#define MMA16816(D, A, b0v, b1v) \
    asm volatile("mma.sync.aligned.m16n8k16.row.col.f32.bf16.bf16.f32 " \
                 "{%0,%1,%2,%3},{%4,%5,%6,%7},{%8,%9},{%0,%1,%2,%3};" \
                 : "+f"((D)[0]), "+f"((D)[1]), "+f"((D)[2]), "+f"((D)[3]) \
                 : "r"((A)[0]), "r"((A)[1]), "r"((A)[2]), "r"((A)[3]), \
                   "r"(b0v), "r"(b1v))

// fp16 MMA, f32 accumulate (GEMM main term)
#define MMA16816_HF32(D, A, b0v, b1v) \
    asm volatile("mma.sync.aligned.m16n8k16.row.col.f32.f16.f16.f32 " \
                 "{%0,%1,%2,%3},{%4,%5,%6,%7},{%8,%9},{%0,%1,%2,%3};" \
                 : "+f"((D)[0]), "+f"((D)[1]), "+f"((D)[2]), "+f"((D)[3]) \
                 : "r"((A)[0]), "r"((A)[1]), "r"((A)[2]), "r"((A)[3]), \
                   "r"(b0v), "r"(b1v))

// fp16 MMA, f16 accumulate (GEMM correction term)
#define MMA16816_HF16(D, A, b0v, b1v) \
    asm volatile("mma.sync.aligned.m16n8k16.row.col.f16.f16.f16.f16 " \
                 "{%0,%1},{%2,%3,%4,%5},{%6,%7},{%0,%1};" \
                 : "+r"((D)[0]), "+r"((D)[1]) \
                 : "r"((A)[0]), "r"((A)[1]), "r"((A)[2]), "r"((A)[3]), \
                   "r"(b0v), "r"(b1v))

__device__ __forceinline__ uint32_t pack_bf16x2(float a, float b) {
    __nv_bfloat162 v = __floats2bfloat162_rn(a, b);
    return *(uint32_t*)&v;
}
__device__ __forceinline__ uint32_t pack_h2(float a, float b) {
    __half2 v = __floats2half2_rn(a, b);
    return *(uint32_t*)&v;
}

// ---------------------------------------------------------------------------
// fp32 -> fp16 hi + scaled lo (weights)
// ---------------------------------------------------------------------------
__global__ __launch_bounds__(256) void split_kernel(
    const float* __restrict__ src, __half* __restrict__ hi,
    __half* __restrict__ lo, int n4)
{
    int i = blockIdx.x * blockDim.x + threadIdx.x;
    if (i >= n4) return;
    float4 v = ((const float4*)src)[i];
    union { __half b[4]; uint2 u; } uh, ul;
    float f[4] = {v.x, v.y, v.z, v.w};
#pragma unroll
    for (int j = 0; j < 4; j++) {
        __half h = __float2half_rn(f[j]);
        uh.b[j] = h;
        ul.b[j] = __float2half_rn((f[j] - __half2float(h)) * LO_SCALE);
    }
    ((uint2*)hi)[i] = uh.u;
    ((uint2*)lo)[i] = ul.u;
}

// fp32 -> fp16 (activations, hi only)
__global__ __launch_bounds__(256) void conv_kernel(
    const float* __restrict__ src, __half* __restrict__ hi, int n4)
{
    int i = blockIdx.x * blockDim.x + threadIdx.x;
    if (i >= n4) return;
    float4 v = ((const float4*)src)[i];
    union { __half b[4]; uint2 u; } uh;
    uh.b[0] = __float2half_rn(v.x);
    uh.b[1] = __float2half_rn(v.y);
    uh.b[2] = __float2half_rn(v.z);
    uh.b[3] = __float2half_rn(v.w);
    ((uint2*)hi)[i] = uh.u;
}

// ---------------------------------------------------------------------------
// 2-term fp16 GEMM: C = Ah@(Wh+Wl)^T + bias
//   main Ah*Wh -> f32 acc;  corr Ah*Wl(x4096) -> f16 acc, /4096 in epilogue.
// 512 threads, 16 warps 4x4, warp tile 32x32. CTA 128x128, KT=64, NSTAGE=3
// (166KB smem, 1 CTA/SM), single barrier per k-iter.
// MODE 0: fp32 C store.  MODE 1: QKV split-store to bf16 head-sep arrays.
// ---------------------------------------------------------------------------
#define KT        64
#define RSTRIDE   144
#define TILE_B    (128 * RSTRIDE)     // 18432
#define STAGE_B   (3 * TILE_B)        // 55296 (Ah, Wh, Wl)
#define NSTAGE    3
#define GEMM_SMEM (NSTAGE * STAGE_B)  // 165888
#define GTHREADS  512

template<int MODE>
__global__ __launch_bounds__(GTHREADS, 1) void gemm_mma_kernel(
    const __half* __restrict__ Ah,
    const __half* __restrict__ Wh, const __half* __restrict__ Wl,
    const float* __restrict__ bias, float* __restrict__ C, int N, int K,
    __nv_bfloat16* __restrict__ oqh, __nv_bfloat16* __restrict__ oql,
    __nv_bfloat16* __restrict__ okh, __nv_bfloat16* __restrict__ okl,
    __nv_bfloat16* __restrict__ ovh, __nv_bfloat16* __restrict__ ovl)
{
    extern __shared__ char smem[];
    const uint32_t sb = smem_u32(smem);
    const int tid  = threadIdx.x;
    const int wid  = tid >> 5;
    const int lane = tid & 31;
    const int wm   = wid & 3;        // 0..3 -> 32-row slice
    const int wn   = wid >> 2;       // 0..3 -> 32-col slice
    const int m0   = blockIdx.y * 128;
    const int n0   = blockIdx.x * 128;

    float    accm[2][4][4];          // main, f32
    uint32_t accc[2][4][2];          // corr, f16x2
#pragma unroll
    for (int a = 0; a < 2; a++)
#pragma unroll
        for (int b = 0; b < 4; b++) {
#pragma unroll
            for (int c = 0; c < 4; c++) accm[a][b][c] = 0.f;
            accc[a][b][0] = 0u; accc[a][b][1] = 0u;
        }

    const int nkc = K / KT;   // 12

    // ---- stage loader: 3072 16B-chunks, 6 per thread ----
    auto issue_stage = [&](int kc, int s) {
        const int k0 = kc * KT;
        const uint32_t sbase = sb + s * STAGE_B;
#pragma unroll
        for (int it = 0; it < 6; it++) {
            const int lin  = it * GTHREADS + tid;  // 0..3071
            const int tile = lin >> 10;            // 0..2
            const int idx  = lin & 1023;
            const int r    = idx >> 3;
            const int c    = idx & 7;
            const uint32_t dst = sbase + tile * TILE_B + r * RSTRIDE + c * 16;
            const __half* src;
            if (tile == 0)      src = Ah + (size_t)(m0 + r) * K + k0 + c * 8;
            else if (tile == 1) src = Wh + (size_t)(n0 + r) * K + k0 + c * 8;
            else                src = Wl + (size_t)(n0 + r) * K + k0 + c * 8;
            CP16(dst, src);
        }
        CP_COMMIT();
    };

    issue_stage(0, 0);
    issue_stage(1, 1);

    const int arow_base = wm * 32 + (lane & 15);
    const int aco       = (lane >> 4);
    const int brow_base = wn * 32 + (((lane >> 4) << 3) | (lane & 7));
    const int bco       = ((lane >> 3) & 1);

    for (int kc = 0; kc < nkc; kc++) {
        CP_WAIT1();
        __syncthreads();
        if (kc + 2 < nkc) issue_stage(kc + 2, (kc + 2) % NSTAGE);
        else CP_COMMIT();

        const uint32_t sbase = sb + (kc % NSTAGE) * STAGE_B;
#pragma unroll
        for (int j = 0; j < 4; j++) {          // four k16 steps per stage
            uint32_t ah[2][4];
#pragma unroll
            for (int mt = 0; mt < 2; mt++) {
                const uint32_t ad = sbase + (arow_base + mt * 16) * RSTRIDE
                                  + j * 32 + aco * 16;
                LDSM4(ah[mt], ad);
            }
#pragma unroll
            for (int ng = 0; ng < 2; ng++) {
                uint32_t bh[4], bl[4];
                const uint32_t bd = sbase + TILE_B
                                  + (brow_base + ng * 16) * RSTRIDE
                                  + j * 32 + bco * 16;
                LDSM4(bh, bd);
                LDSM4(bl, bd + TILE_B);
#pragma unroll
                for (int mt = 0; mt < 2; mt++)
#pragma unroll
                    for (int p = 0; p < 2; p++) {
                        MMA16816_HF32(accm[mt][ng * 2 + p], ah[mt],
                                      bh[2 * p], bh[2 * p + 1]);
                        MMA16816_HF16(accc[mt][ng * 2 + p], ah[mt],
                                      bl[2 * p], bl[2 * p + 1]);
                    }
            }
        }
    }

    const int g = lane >> 2;
    const int t = lane & 3;
#pragma unroll
    for (int mt = 0; mt < 2; mt++) {
        const int row0 = m0 + wm * 32 + mt * 16 + g;
#pragma unroll
        for (int nt = 0; nt < 4; nt++) {
            const int col = n0 + wn * 32 + nt * 8 + t * 2;
            const float2 bv = *(const float2*)&bias[col];
            const float2 c0 = __half22float2(*(__half2*)&accc[mt][nt][0]);
            const float2 c1 = __half22float2(*(__half2*)&accc[mt][nt][1]);
            float v00 = accm[mt][nt][0] + c0.x * LO_INV + bv.x;
            float v01 = accm[mt][nt][1] + c0.y * LO_INV + bv.y;
            float v10 = accm[mt][nt][2] + c1.x * LO_INV + bv.x;
            float v11 = accm[mt][nt][3] + c1.y * LO_INV + bv.y;
            if (MODE == 0) {
                *(float2*)&C[(size_t)row0 * N + col]       = make_float2(v00, v01);
                *(float2*)&C[(size_t)(row0 + 8) * N + col] = make_float2(v10, v11);
            } else {
                const int sec = col / 768;
                const int rem = col - sec * 768;
                const int h   = rem >> 6;
                const int d   = rem & 63;
                if (sec == 0) { v00 *= 0.125f; v01 *= 0.125f; v10 *= 0.125f; v11 *= 0.125f; }
                __nv_bfloat16* dh = (sec == 0) ? oqh : (sec == 1) ? okh : ovh;
                __nv_bfloat16* dl = (sec == 0) ? oql : (sec == 1) ? okl : ovl;
#pragma unroll
                for (int rr = 0; rr < 2; rr++) {
                    const int row = row0 + rr * 8;
                    const float a0 = rr ? v10 : v00, a1 = rr ? v11 : v01;
                    const int bb = row >> 9, ss = row & 511;
                    const size_t idx = (((size_t)bb * H_ + h) * S_ + ss) * HD_ + d;
                    const float h0 = __bfloat162float(__float2bfloat16_rn(a0));
                    const float h1 = __bfloat162float(__float2bfloat16_rn(a1));
                    *(uint32_t*)&dh[idx] = pack_bf16x2(a0, a1);
                    *(uint32_t*)&dl[idx] = pack_bf16x2(a0 - h0, a1 - h1);
                }
            }
        }
    }
}

// ---------------------------------------------------------------------------
// Tensor-core flash attention (3-term bf16, core unchanged since R6;
// epilogue writes fp16 hi only for the 2-term proj GEMM).
// Grid (S/128, H, B), 256 threads (8 warps x 16 q-rows). kv tiles of 64.
// ---------------------------------------------------------------------------
#define ARS      144
#define QT_B     (128 * ARS)
#define AT_B     (64 * ARS)
#define ASTAGE_B (4 * AT_B)
#define ATT_SMEM (2 * QT_B + 2 * ASTAGE_B)

__global__ __launch_bounds__(256, 2) void attn_tc_kernel()
{
    extern __shared__ char smem[];
    const uint32_t sb = smem_u32(smem);
    const uint32_t QH = sb, QL = sb + QT_B;
    const int tid  = threadIdx.x;
    const int wid  = tid >> 5;
    const int lane = tid & 31;
    const int g    = lane >> 2;
    const int t    = lane & 3;

    const int qt = blockIdx.x;
    const int h  = blockIdx.y;
    const int b  = blockIdx.z;

    const size_t headbase = ((size_t)b * H_ + h) * S_ * HD_;
    const size_t qbase    = headbase + (size_t)qt * 128 * HD_;

#pragma unroll
    for (int it = 0; it < 8; it++) {
        const int lin  = it * 256 + tid;
        const int half = lin >> 10;
        const int idx  = lin & 1023;
        const int r    = idx >> 3;
        const int c    = idx & 7;
        const uint32_t dst = (half ? QL : QH) + r * ARS + c * 16;
        const __nv_bfloat16* src = (half ? g_ql : g_qh) + qbase + (size_t)r * HD_ + c * 8;
        CP16(dst, src);
    }
    CP_COMMIT();

    auto issue_kv = [&](int kt, int s) {
        const uint32_t sbase = sb + 2 * QT_B + s * ASTAGE_B;
        const size_t kvb = headbase + (size_t)kt * 64 * HD_;
#pragma unroll
        for (int it = 0; it < 8; it++) {
            const int lin  = it * 256 + tid;
            const int tile = lin >> 9;
            const int idx  = lin & 511;
            const int r    = idx >> 3;
            const int c    = idx & 7;
            const uint32_t dst = sbase + tile * AT_B + r * ARS + c * 16;
            const __nv_bfloat16* base =
                (tile == 0) ? g_kh : (tile == 1) ? g_kl : (tile == 2) ? g_vh : g_vl;
            CP16(dst, base + kvb + (size_t)r * HD_ + c * 8);
        }
        CP_COMMIT();
    };

    issue_kv(0, 0);
    issue_kv(1, 1);

    float oacc[8][4];
#pragma unroll
    for (int j = 0; j < 8; j++)
#pragma unroll
        for (int c = 0; c < 4; c++) oacc[j][c] = 0.f;
    float mrow[2] = {-1e30f, -1e30f};
    float lrow[2] = {0.f, 0.f};

    const int qa_row = wid * 16 + (lane & 15);
    const int qa_k   = (lane >> 4) * 8;
    const int kb_row = (lane & 7) + 8 * (lane >> 4);
    const int kb_k   = ((lane >> 3) & 1) * 8;
    const int vb_row = (lane & 15);
    const int vb_d   = (lane >> 4) * 8;

    for (int kt = 0; kt < 8; kt++) {
        CP_WAIT1();
        __syncthreads();
        const uint32_t st  = sb + 2 * QT_B + (kt & 1) * ASTAGE_B;
        const uint32_t KHs = st, VHs = st + 2 * AT_B;

        float sacc[8][4];
#pragma unroll
        for (int j = 0; j < 8; j++)
#pragma unroll
            for (int c = 0; c < 4; c++) sacc[j][c] = 0.f;

#pragma unroll
        for (int ks = 0; ks < 4; ks++) {
            uint32_t qh[4], ql[4];
            const uint32_t qa = QH + qa_row * ARS + (ks * 16 + qa_k) * 2;
            LDSM4(qh, qa);
            LDSM4(ql, qa + QT_B);
#pragma unroll
            for (int jp = 0; jp < 4; jp++) {
                uint32_t kh[4], kl[4];
                const uint32_t ka = KHs + (jp * 16 + kb_row) * ARS + (ks * 16 + kb_k) * 2;
                LDSM4(kh, ka);
                LDSM4(kl, ka + AT_B);
                MMA16816(sacc[2 * jp],     qh, kh[0], kh[1]);
                MMA16816(sacc[2 * jp + 1], qh, kh[2], kh[3]);
                MMA16816(sacc[2 * jp],     qh, kl[0], kl[1]);
                MMA16816(sacc[2 * jp + 1], qh, kl[2], kl[3]);
                MMA16816(sacc[2 * jp],     ql, kh[0], kh[1]);
                MMA16816(sacc[2 * jp + 1], ql, kh[2], kh[3]);
            }
        }

        float mloc0 = -1e30f, mloc1 = -1e30f;
#pragma unroll
        for (int j = 0; j < 8; j++) {
            mloc0 = fmaxf(mloc0, fmaxf(sacc[j][0], sacc[j][1]));
            mloc1 = fmaxf(mloc1, fmaxf(sacc[j][2], sacc[j][3]));
        }
        mloc0 = fmaxf(mloc0, __shfl_xor_sync(0xffffffffu, mloc0, 1));
        mloc0 = fmaxf(mloc0, __shfl_xor_sync(0xffffffffu, mloc0, 2));
        mloc1 = fmaxf(mloc1, __shfl_xor_sync(0xffffffffu, mloc1, 1));
        mloc1 = fmaxf(mloc1, __shfl_xor_sync(0xffffffffu, mloc1, 2));

        const float nm0 = fmaxf(mrow[0], mloc0);
        const float nm1 = fmaxf(mrow[1], mloc1);
        const float cr0 = __expf(mrow[0] - nm0);
        const float cr1 = __expf(mrow[1] - nm1);
        mrow[0] = nm0; mrow[1] = nm1;
        lrow[0] *= cr0; lrow[1] *= cr1;
#pragma unroll
        for (int j = 0; j < 8; j++) {
            oacc[j][0] *= cr0; oacc[j][1] *= cr0;
            oacc[j][2] *= cr1; oacc[j][3] *= cr1;
        }
        float ll0 = 0.f, ll1 = 0.f;
#pragma unroll
        for (int j = 0; j < 8; j++) {
            sacc[j][0] = __expf(sacc[j][0] - nm0);
            sacc[j][1] = __expf(sacc[j][1] - nm0);
            sacc[j][2] = __expf(sacc[j][2] - nm1);
            sacc[j][3] = __expf(sacc[j][3] - nm1);
            ll0 += sacc[j][0] + sacc[j][1];
            ll1 += sacc[j][2] + sacc[j][3];
        }
        ll0 += __shfl_xor_sync(0xffffffffu, ll0, 1);
        ll0 += __shfl_xor_sync(0xffffffffu, ll0, 2);
        ll1 += __shfl_xor_sync(0xffffffffu, ll1, 1);
        ll1 += __shfl_xor_sync(0xffffffffu, ll1, 2);
        lrow[0] += ll0; lrow[1] += ll1;

#pragma unroll
        for (int i = 0; i < 4; i++) {
            uint32_t pah[4], pal[4];
#pragma unroll
            for (int hf = 0; hf < 2; hf++) {
                const float* sp = sacc[2 * i + hf];
                float h0 = __bfloat162float(__float2bfloat16_rn(sp[0]));
                float h1 = __bfloat162float(__float2bfloat16_rn(sp[1]));
                float h2 = __bfloat162float(__float2bfloat16_rn(sp[2]));
                float h3 = __bfloat162float(__float2bfloat16_rn(sp[3]));
                pah[2 * hf]     = pack_bf16x2(sp[0], sp[1]);
                pah[2 * hf + 1] = pack_bf16x2(sp[2], sp[3]);
                pal[2 * hf]     = pack_bf16x2(sp[0] - h0, sp[1] - h1);
                pal[2 * hf + 1] = pack_bf16x2(sp[2] - h2, sp[3] - h3);
            }
            uint32_t Ah4[4] = {pah[0], pah[1], pah[2], pah[3]};
            uint32_t Al4[4] = {pal[0], pal[1], pal[2], pal[3]};
#pragma unroll
            for (int dv = 0; dv < 4; dv++) {
                uint32_t vh[4], vl[4];
                const uint32_t va = VHs + (i * 16 + vb_row) * ARS + (dv * 16 + vb_d) * 2;
                LDSM4T(vh, va);
                LDSM4T(vl, va + AT_B);
                MMA16816(oacc[2 * dv],     Ah4, vh[0], vh[1]);
                MMA16816(oacc[2 * dv + 1], Ah4, vh[2], vh[3]);
                MMA16816(oacc[2 * dv],     Ah4, vl[0], vl[1]);
                MMA16816(oacc[2 * dv + 1], Ah4, vl[2], vl[3]);
                MMA16816(oacc[2 * dv],     Al4, vh[0], vh[1]);
                MMA16816(oacc[2 * dv + 1], Al4, vh[2], vh[3]);
            }
        }

        __syncthreads();
        if (kt + 2 < 8) issue_kv(kt + 2, kt & 1);
    }

    // epilogue: normalize, write fp16 hi only (proj is 2-term)
    const float inv0 = 1.f / lrow[0];
    const float inv1 = 1.f / lrow[1];
    const int s0 = qt * 128 + wid * 16 + g;
#pragma unroll
    for (int rr = 0; rr < 2; rr++) {
        const int srow = s0 + rr * 8;
        const float inv = rr ? inv1 : inv0;
        const size_t obase = ((size_t)b * S_ + srow) * D_ + h * HD_;
#pragma unroll
        for (int j = 0; j < 8; j++) {
            const int d = j * 8 + t * 2;
            const float a0 = oacc[j][2 * rr]     * inv;
            const float a1 = oacc[j][2 * rr + 1] * inv;
            *(uint32_t*)&g_ah[obase + d] = pack_h2(a0, a1);
        }
    }
}

// ---------------------------------------------------------------------------
extern "C" void kernel_launch(void* const* d_in, const int* in_sizes, int n_in,
                              void* d_out, int out_size)
{
    const float* x      = (const float*)d_in[0];
    const float* qkv_w  = (const float*)d_in[1];
    const float* qkv_b  = (const float*)d_in[2];
    const float* proj_w = (const float*)d_in[3];
    const float* proj_b = (const float*)d_in[4];
    float* out = (float*)d_out;

    __half *xh, *ah, *qwh, *qwl, *pwh, *pwl;
    __nv_bfloat16 *qh, *ql, *kh, *kl, *vh, *vl;
    cudaGetSymbolAddress((void**)&xh, g_xh);
    cudaGetSymbolAddress((void**)&ah, g_ah);
    cudaGetSymbolAddress((void**)&qwh, g_qwh);
    cudaGetSymbolAddress((void**)&qwl, g_qwl);
    cudaGetSymbolAddress((void**)&pwh, g_pwh);
    cudaGetSymbolAddress((void**)&pwl, g_pwl);
    cudaGetSymbolAddress((void**)&qh, g_qh);
    cudaGetSymbolAddress((void**)&ql, g_ql);
    cudaGetSymbolAddress((void**)&kh, g_kh);
    cudaGetSymbolAddress((void**)&kl, g_kl);
    cudaGetSymbolAddress((void**)&vh, g_vh);
    cudaGetSymbolAddress((void**)&vl, g_vl);

    cudaFuncSetAttribute(gemm_mma_kernel<0>,
                         cudaFuncAttributeMaxDynamicSharedMemorySize, GEMM_SMEM);
    cudaFuncSetAttribute(gemm_mma_kernel<1>,
                         cudaFuncAttributeMaxDynamicSharedMemorySize, GEMM_SMEM);
    cudaFuncSetAttribute(attn_tc_kernel,
                         cudaFuncAttributeMaxDynamicSharedMemorySize, ATT_SMEM);

    // 1) conversions: x -> fp16 hi; weights -> fp16 hi + scaled lo
    {
        int n4 = (M_ * D_) / 4;
        conv_kernel<<<(n4 + 255) / 256, 256>>>(x, xh, n4);
        n4 = (NQKV * D_) / 4;
        split_kernel<<<(n4 + 255) / 256, 256>>>(qkv_w, qwh, qwl, n4);
        n4 = (D_ * D_) / 4;
        split_kernel<<<(n4 + 255) / 256, 256>>>(proj_w, pwh, pwl, n4);
    }

    // 2) QKV projection -> bf16 head-separated (Q pre-scaled)
    {
        dim3 g(NQKV / 128, M_ / 128);
        gemm_mma_kernel<1><<<g, GTHREADS, GEMM_SMEM>>>(xh, qwh, qwl, qkv_b,
                                                       nullptr, NQKV, D_,
                                                       qh, ql, kh, kl, vh, vl);
    }

    // 3) tensor-core flash attention -> g_ah (fp16)
    {
        dim3 g(S_ / 128, H_, B_);
        attn_tc_kernel<<<g, 256, ATT_SMEM>>>();
    }

    // 4) output projection
    {
        dim3 g(D_ / 128, M_ / 128);
        gemm_mma_kernel<0><<<g, GTHREADS, GEMM_SMEM>>>(ah, pwh, pwl, proj_b, out,
                                                       D_, D_,
                                                       nullptr, nullptr, nullptr,
                                                       nullptr, nullptr, nullptr);
    }
}